// round 11
// baseline (speedup 1.0000x reference)
#include <cuda_runtime.h>
#include <math.h>

// Problem constants
#define BATCH   4
#define NNODES  325
#define BN      (BATCH * NNODES)   // 1300
#define IDIM    64
#define HDIM    128
#define G4H     (4 * HDIM)         // 512
#define MAXNB   96
#define LN_EPS  1e-5f

// ---------------- scratch (__device__ globals; no allocation) ----------------
__device__ float g_gates[BN * G4H];
__device__ float g_h_lstm[BN * HDIM];
__device__ float g_support[BN * HDIM];
__device__ float g_hgraph[BN * HDIM];
__device__ float g_P[BN * HDIM];          // support @ Ws^T
__device__ float g_Q[BN * HDIM];          // support @ Wt^T
__device__ float g_s[BN * HDIM];
__device__ float g_t[BN * HDIM];
__device__ float g_hatt[BN * HDIM];
__device__ int   g_nbr[BN * MAXNB];
__device__ float g_nbrw[BN * MAXNB];
__device__ int   g_cnt[BN];
__device__ float g_sconst[HDIM];          // gc_b @ Ws^T + Ws_b
__device__ float g_tconst[HDIM];          // gc_b @ Wt^T + Wt_b
// transposed weights (coalesced GEMM access)
__device__ float g_Wih_t[IDIM * G4H];        // [64][512]
__device__ float g_Whh_t[HDIM * G4H];        // [128][512]
__device__ float g_Wst_t[HDIM * 2 * HDIM];   // [128][256]: col<128 Ws, col>=128 Wt
__device__ float g_comb_t[2 * HDIM * HDIM];  // [256][128]

__device__ __forceinline__ float sigm_fast(float x) {
    return __fdividef(1.0f, 1.0f + __expf(-x));
}
__device__ __forceinline__ float tanh_fast(float x) {
    float cx = fminf(fmaxf(x, -15.0f), 15.0f);
    float e = __expf(2.0f * cx);
    return __fdividef(e - 1.0f, e + 1.0f);
}

// ============================================================================
// K0: prep = weight transposes + adjacency scan + s/t bias-constants.
// ============================================================================
#define TW_TOTAL (IDIM*G4H + HDIM*G4H + HDIM*2*HDIM + 2*HDIM*HDIM)
#define NTB ((TW_TOTAL + 255) / 256)
#define SCANB ((BN + 7) / 8)
__global__ void __launch_bounds__(256)
prep_kernel(const float* __restrict__ W_ih, const float* __restrict__ W_hh,
            const float* __restrict__ Ws_w, const float* __restrict__ Wt_w,
            const float* __restrict__ comb_w, const float* __restrict__ adj,
            const float* __restrict__ gc_b, const float* __restrict__ Ws_b,
            const float* __restrict__ Wt_b)
{
    if (blockIdx.x < NTB) {
        int idx = blockIdx.x * 256 + threadIdx.x;
        if (idx < IDIM * G4H) {                       // Wih_t [64][512]
            int k = idx >> 9, g = idx & 511;
            g_Wih_t[idx] = __ldg(W_ih + g * IDIM + k);
            return;
        }
        idx -= IDIM * G4H;
        if (idx < HDIM * G4H) {                       // Whh_t [128][512]
            int k = idx >> 9, g = idx & 511;
            g_Whh_t[idx] = __ldg(W_hh + g * HDIM + k);
            return;
        }
        idx -= HDIM * G4H;
        if (idx < HDIM * 2 * HDIM) {                  // Wst_t [128][256]
            int k = idx >> 8, o = idx & 255;
            g_Wst_t[idx] = (o < HDIM) ? __ldg(Ws_w + o * HDIM + k)
                                      : __ldg(Wt_w + (o - HDIM) * HDIM + k);
            return;
        }
        idx -= HDIM * 2 * HDIM;
        if (idx < 2 * HDIM * HDIM) {                  // comb_t [256][128]
            int k = idx >> 7, o = idx & 127;
            g_comb_t[idx] = __ldg(comb_w + o * 2 * HDIM + k);
        }
        return;
    }

    if (blockIdx.x < NTB + SCANB) {
        // ---- adjacency scan: 8 warps, one row per warp, ballot compaction ----
        const int lane = threadIdx.x & 31;
        const int wrp  = threadIdx.x >> 5;
        const int row  = (blockIdx.x - NTB) * 8 + wrp;
        if (row >= BN) return;
        const int b = row / NNODES;
        const int i = row % NNODES;
        const float* arow = adj + (size_t)b * NNODES * NNODES + (size_t)i * NNODES;

        int cnt = 0;
        const unsigned lt = (1u << lane) - 1u;
        for (int j0 = 0; j0 < NNODES; j0 += 32) {
            int j = j0 + lane;
            float a = (j < NNODES) ? __ldg(arow + j) : 0.0f;
            unsigned m = __ballot_sync(0xffffffffu, a != 0.0f);
            int pos = cnt + __popc(m & lt);
            if (a != 0.0f && pos < MAXNB) {
                g_nbr[row * MAXNB + pos]  = j;
                g_nbrw[row * MAXNB + pos] = a;
            }
            cnt += __popc(m);
        }
        if (lane == 0) g_cnt[row] = min(cnt, MAXNB);
        return;
    }

    // ---- bias constants: sconst = gc_b @ Ws^T + Ws_b; tconst likewise ----
    __shared__ float gb[HDIM];
    int tid = threadIdx.x;
    if (tid < HDIM) gb[tid] = __ldg(gc_b + tid);
    __syncthreads();
    int o = tid & 127;
    const float* W = (tid < HDIM) ? (Ws_w + o * HDIM) : (Wt_w + o * HDIM);
    float acc = (tid < HDIM) ? __ldg(Ws_b + o) : __ldg(Wt_b + o);
#pragma unroll 8
    for (int k = 0; k < HDIM; k++)
        acc += gb[k] * __ldg(W + k);
    if (tid < HDIM) g_sconst[o] = acc;
    else            g_tconst[o] = acc;
}

// ============================================================================
// K1: LSTM gates GEMM.  Grid (163, 4), 128 thr, 8 nodes/block.
// ============================================================================
#define LNT 8
__global__ void __launch_bounds__(128)
lstm_gemm_kernel(const float* __restrict__ x, const float* __restrict__ h,
                 const float* __restrict__ b_ih, const float* __restrict__ b_hh)
{
    __shared__ __align__(16) float sx[LNT][IDIM];
    __shared__ __align__(16) float sh[LNT][HDIM];

    const int node0 = blockIdx.x * LNT;
    const int o = threadIdx.x;
    const int g = blockIdx.y * HDIM + o;

    for (int idx = o; idx < LNT * IDIM; idx += 128) {
        int m = idx >> 6, k = idx & 63;
        int node = node0 + m;
        sx[m][k] = (node < BN) ? x[node * IDIM + k] : 0.0f;
    }
    for (int idx = o; idx < LNT * HDIM; idx += 128) {
        int m = idx >> 7, k = idx & 127;
        int node = node0 + m;
        sh[m][k] = (node < BN) ? h[node * HDIM + k] : 0.0f;
    }
    __syncthreads();

    float acc[LNT];
    const float bb = __ldg(b_ih + g) + __ldg(b_hh + g);
#pragma unroll
    for (int m = 0; m < LNT; m++) acc[m] = bb;

#pragma unroll 4
    for (int k4 = 0; k4 < IDIM / 4; k4++) {
        int k = k4 * 4;
        float w0 = g_Wih_t[(k + 0) * G4H + g];
        float w1 = g_Wih_t[(k + 1) * G4H + g];
        float w2 = g_Wih_t[(k + 2) * G4H + g];
        float w3 = g_Wih_t[(k + 3) * G4H + g];
#pragma unroll
        for (int m = 0; m < LNT; m++) {
            float4 a = *((const float4*)&sx[m][k]);
            acc[m] += a.x * w0 + a.y * w1 + a.z * w2 + a.w * w3;
        }
    }
#pragma unroll 4
    for (int k4 = 0; k4 < HDIM / 4; k4++) {
        int k = k4 * 4;
        float w0 = g_Whh_t[(k + 0) * G4H + g];
        float w1 = g_Whh_t[(k + 1) * G4H + g];
        float w2 = g_Whh_t[(k + 2) * G4H + g];
        float w3 = g_Whh_t[(k + 3) * G4H + g];
#pragma unroll
        for (int m = 0; m < LNT; m++) {
            float4 a = *((const float4*)&sh[m][k]);
            acc[m] += a.x * w0 + a.y * w1 + a.z * w2 + a.w * w3;
        }
    }
#pragma unroll
    for (int m = 0; m < LNT; m++) {
        int node = node0 + m;
        if (node < BN) g_gates[node * G4H + g] = acc[m];
    }
}

// ============================================================================
// K2: LSTM activations + support GEMM (m=2).  650 blocks, 128 threads.
// ============================================================================
__global__ void __launch_bounds__(128)
act_support_kernel(const float* __restrict__ c, const float* __restrict__ gc_w,
                   float* __restrict__ c_out)
{
    __shared__ float shh[2][HDIM];
    const int node0 = blockIdx.x * 2;
    const int u = threadIdx.x;

#pragma unroll
    for (int m = 0; m < 2; m++) {
        int node = node0 + m;
        const float* gb = g_gates + node * G4H;
        float ig = sigm_fast(gb[u]);
        float fg = sigm_fast(gb[HDIM + u]);
        float gg = tanh_fast(gb[2 * HDIM + u]);
        float og = sigm_fast(gb[3 * HDIM + u]);
        float cc = fg * c[node * HDIM + u] + ig * gg;
        float hh = og * tanh_fast(cc);
        c_out[node * HDIM + u] = cc;
        g_h_lstm[node * HDIM + u] = hh;
        shh[m][u] = hh;
    }
    __syncthreads();

    const int o = u;
    float a0 = 0.f, a1 = 0.f;
#pragma unroll 4
    for (int k = 0; k < HDIM; k++) {
        float w = __ldg(gc_w + k * HDIM + o);
        a0 += shh[0][k] * w;
        a1 += shh[1][k] * w;
    }
    g_support[node0 * HDIM + o] = a0;
    g_support[(node0 + 1) * HDIM + o] = a1;
}

// ============================================================================
// K3: P|Q dense GEMM:  P = support @ Ws^T, Q = support @ Wt^T.
// Grid (163, 2): y=0 -> P (Ws), y=1 -> Q (Wt).  8 nodes/block, 128 threads.
// ============================================================================
__global__ void __launch_bounds__(128)
pq_kernel()
{
    __shared__ __align__(16) float sA[LNT][HDIM];
    const int node0 = blockIdx.x * LNT;
    const int o = threadIdx.x;
    const int oc = blockIdx.y * HDIM + o;   // column in fused Wst

    for (int idx = o; idx < LNT * HDIM; idx += 128) {
        int m = idx >> 7, k = idx & 127;
        int node = node0 + m;
        sA[m][k] = (node < BN) ? g_support[node * HDIM + k] : 0.0f;
    }
    __syncthreads();

    float acc[LNT];
#pragma unroll
    for (int m = 0; m < LNT; m++) acc[m] = 0.0f;

#pragma unroll 4
    for (int k4 = 0; k4 < HDIM / 4; k4++) {
        int k = k4 * 4;
        float w0 = g_Wst_t[(k + 0) * 2 * HDIM + oc];
        float w1 = g_Wst_t[(k + 1) * 2 * HDIM + oc];
        float w2 = g_Wst_t[(k + 2) * 2 * HDIM + oc];
        float w3 = g_Wst_t[(k + 3) * 2 * HDIM + oc];
#pragma unroll
        for (int m = 0; m < LNT; m++) {
            float4 a = *((const float4*)&sA[m][k]);
            acc[m] += a.x * w0 + a.y * w1 + a.z * w2 + a.w * w3;
        }
    }
    float* C = blockIdx.y ? g_Q : g_P;
#pragma unroll
    for (int m = 0; m < LNT; m++) {
        int node = node0 + m;
        if (node < BN) C[node * HDIM + o] = acc[m];
    }
}

// ============================================================================
// K4: triple sparse gather (no weights!).  Block-per-row: 1300 blocks, 128 thr.
//   hgraph = adj-gather(support) + gc_b
//   s      = adj-gather(P) + sconst
//   t      = adj-gather(Q) + tconst
// ============================================================================
__global__ void __launch_bounds__(128)
gather_kernel(const float* __restrict__ gc_b)
{
    const int row = blockIdx.x;
    const int b = row / NNODES;
    const int tid = threadIdx.x;

    __shared__ int   lst[MAXNB];
    __shared__ float wv[MAXNB];

    const int cn = g_cnt[row];
    for (int t = tid; t < cn; t += 128) {
        lst[t] = g_nbr[row * MAXNB + t];
        wv[t]  = g_nbrw[row * MAXNB + t];
    }
    __syncthreads();

    const int u = tid;
    float ah = __ldg(gc_b + u);
    float as = g_sconst[u];
    float at = g_tconst[u];
    const size_t base = (size_t)b * NNODES * HDIM + u;
    for (int t = 0; t < cn; t++) {
        size_t off = base + (size_t)lst[t] * HDIM;
        float w = wv[t];
        ah += w * g_support[off];
        as += w * g_P[off];
        at += w * g_Q[off];
    }
    g_hgraph[row * HDIM + u] = ah;
    g_s[row * HDIM + u] = as;
    g_t[row * HDIM + u] = at;
}

// ============================================================================
// K5: attention + softmax + context + LayerNorm (no combine).
// Block-per-row: 1300 blocks, 128 threads = 4 warps.
// ============================================================================
__global__ void __launch_bounds__(128)
attn_kernel(const float* __restrict__ v, const float* __restrict__ ln_g,
            const float* __restrict__ ln_b)
{
    const int row = blockIdx.x;
    const int b = row / NNODES;
    const int tid = threadIdx.x;
    const int lane = tid & 31;
    const int wrp = tid >> 5;

    __shared__ float s_sh[HDIM];
    __shared__ float v_sh[HDIM];
    __shared__ float sc[MAXNB];
    __shared__ int   lst[MAXNB];
    __shared__ float red1[4], red2[4];

    s_sh[tid] = g_s[row * HDIM + tid];
    v_sh[tid] = __ldg(v + tid);
    const int cn = g_cnt[row];
    for (int t = tid; t < cn; t += 128) lst[t] = g_nbr[row * MAXNB + t];
    __syncthreads();

    // scores: 4 warps t-strided; lanes over features
    const float* tb = g_t + (size_t)b * NNODES * HDIM;
    for (int t = wrp; t < cn; t += 4) {
        const float* tj = tb + (size_t)lst[t] * HDIM;
        float p = 0.0f;
#pragma unroll
        for (int q = 0; q < 4; q++) {
            int u = lane + q * 32;
            p += tanh_fast(s_sh[u] + __ldg(tj + u)) * v_sh[u];
        }
#pragma unroll
        for (int off = 16; off > 0; off >>= 1)
            p += __shfl_xor_sync(0xffffffffu, p, off);
        if (lane == 0) sc[t] = p;
    }
    __syncthreads();

    // softmax (warp 0)
    if (wrp == 0) {
        float mx = -1e30f;
        for (int t = lane; t < cn; t += 32) mx = fmaxf(mx, sc[t]);
#pragma unroll
        for (int off = 16; off > 0; off >>= 1)
            mx = fmaxf(mx, __shfl_xor_sync(0xffffffffu, mx, off));
        float sm = 0.0f;
        for (int t = lane; t < cn; t += 32) {
            float e = __expf(sc[t] - mx);
            sc[t] = e;
            sm += e;
        }
#pragma unroll
        for (int off = 16; off > 0; off >>= 1)
            sm += __shfl_xor_sync(0xffffffffu, sm, off);
        float inv = __fdividef(1.0f, sm);
        for (int t = lane; t < cn; t += 32) sc[t] *= inv;
    }
    __syncthreads();

    // context: thread = feature u
    const int u = tid;
    float acc = 0.0f;
    const float* hgb = g_hgraph + (size_t)b * NNODES * HDIM;
    for (int t = 0; t < cn; t++)
        acc += sc[t] * __ldg(hgb + (size_t)lst[t] * HDIM + u);

    // LayerNorm
    float s1 = acc, s2 = acc * acc;
#pragma unroll
    for (int off = 16; off > 0; off >>= 1) {
        s1 += __shfl_xor_sync(0xffffffffu, s1, off);
        s2 += __shfl_xor_sync(0xffffffffu, s2, off);
    }
    if (lane == 0) { red1[wrp] = s1; red2[wrp] = s2; }
    __syncthreads();
    float tot1 = red1[0] + red1[1] + red1[2] + red1[3];
    float tot2 = red2[0] + red2[1] + red2[2] + red2[3];
    float mu = tot1 * (1.0f / HDIM);
    float var = tot2 * (1.0f / HDIM) - mu * mu;
    g_hatt[row * HDIM + u] =
        __ldg(ln_g + u) * (acc - mu) * rsqrtf(var + LN_EPS) + __ldg(ln_b + u);
}

// ============================================================================
// K6: combine dense GEMM:  out = h_lstm @ W1^T + h_att @ W2^T + comb_b.
// 163 blocks, 8 nodes/block, 128 threads, K=256.
// ============================================================================
__global__ void __launch_bounds__(128)
comb_kernel(const float* __restrict__ comb_b, float* __restrict__ out)
{
    __shared__ __align__(16) float shl[LNT][HDIM];
    __shared__ __align__(16) float sha[LNT][HDIM];
    const int node0 = blockIdx.x * LNT;
    const int o = threadIdx.x;

    for (int idx = o; idx < LNT * HDIM; idx += 128) {
        int m = idx >> 7, k = idx & 127;
        int node = node0 + m;
        shl[m][k] = (node < BN) ? g_h_lstm[node * HDIM + k] : 0.0f;
        sha[m][k] = (node < BN) ? g_hatt[node * HDIM + k] : 0.0f;
    }
    __syncthreads();

    float acc[LNT];
    const float cb = __ldg(comb_b + o);
#pragma unroll
    for (int m = 0; m < LNT; m++) acc[m] = cb;

#pragma unroll 4
    for (int k4 = 0; k4 < HDIM / 4; k4++) {
        int k = k4 * 4;
        float w0 = g_comb_t[(k + 0) * HDIM + o];
        float w1 = g_comb_t[(k + 1) * HDIM + o];
        float w2 = g_comb_t[(k + 2) * HDIM + o];
        float w3 = g_comb_t[(k + 3) * HDIM + o];
#pragma unroll
        for (int m = 0; m < LNT; m++) {
            float4 a = *((const float4*)&shl[m][k]);
            acc[m] += a.x * w0 + a.y * w1 + a.z * w2 + a.w * w3;
        }
    }
#pragma unroll 4
    for (int k4 = 0; k4 < HDIM / 4; k4++) {
        int k = k4 * 4;
        float w0 = g_comb_t[(HDIM + k + 0) * HDIM + o];
        float w1 = g_comb_t[(HDIM + k + 1) * HDIM + o];
        float w2 = g_comb_t[(HDIM + k + 2) * HDIM + o];
        float w3 = g_comb_t[(HDIM + k + 3) * HDIM + o];
#pragma unroll
        for (int m = 0; m < LNT; m++) {
            float4 a = *((const float4*)&sha[m][k]);
            acc[m] += a.x * w0 + a.y * w1 + a.z * w2 + a.w * w3;
        }
    }
#pragma unroll
    for (int m = 0; m < LNT; m++) {
        int node = node0 + m;
        if (node < BN) out[node * HDIM + o] = acc[m];
    }
}

// ============================================================================
extern "C" void kernel_launch(void* const* d_in, const int* in_sizes, int n_in,
                              void* d_out, int out_size)
{
    const float* x      = (const float*)d_in[0];
    const float* adj    = (const float*)d_in[1];
    const float* h      = (const float*)d_in[2];
    const float* c      = (const float*)d_in[3];
    const float* W_ih   = (const float*)d_in[4];
    const float* W_hh   = (const float*)d_in[5];
    const float* b_ih   = (const float*)d_in[6];
    const float* b_hh   = (const float*)d_in[7];
    const float* gc_w   = (const float*)d_in[8];
    const float* gc_b   = (const float*)d_in[9];
    const float* Ws_w   = (const float*)d_in[10];
    const float* Ws_b   = (const float*)d_in[11];
    const float* Wt_w   = (const float*)d_in[12];
    const float* Wt_b   = (const float*)d_in[13];
    const float* v      = (const float*)d_in[14];
    const float* ln_g   = (const float*)d_in[15];
    const float* ln_b   = (const float*)d_in[16];
    const float* comb_w = (const float*)d_in[17];
    const float* comb_b = (const float*)d_in[18];

    float* out = (float*)d_out;              // h_new, then c_lstm
    float* c_out = out + (size_t)BN * HDIM;

    prep_kernel<<<NTB + SCANB + 1, 256>>>(W_ih, W_hh, Ws_w, Wt_w, comb_w, adj,
                                          gc_b, Ws_b, Wt_b);
    dim3 lstm_grid((BN + LNT - 1) / LNT, 4);          // 163 x 4
    lstm_gemm_kernel<<<lstm_grid, 128>>>(x, h, b_ih, b_hh);
    act_support_kernel<<<BN / 2, 128>>>(c, gc_w, c_out);          // 650
    dim3 pq_grid((BN + LNT - 1) / LNT, 2);            // 163 x 2
    pq_kernel<<<pq_grid, 128>>>();
    gather_kernel<<<BN, 128>>>(gc_b);                 // 1300
    attn_kernel<<<BN, 128>>>(v, ln_g, ln_b);          // 1300
    comb_kernel<<<(BN + LNT - 1) / LNT, 128>>>(comb_b, out);      // 163
}

// round 14
// speedup vs baseline: 1.1000x; 1.1000x over previous
#include <cuda_runtime.h>
#include <math.h>

// Problem constants
#define BATCH   4
#define NNODES  325
#define BN      (BATCH * NNODES)   // 1300
#define IDIM    64
#define HDIM    128
#define G4H     (4 * HDIM)         // 512
#define MAXNB   96
#define LN_EPS  1e-5f

// ---------------- scratch (__device__ globals; no allocation) ----------------
__device__ float g_gates[BN * G4H];
__device__ float g_h_lstm[BN * HDIM];
__device__ float g_support[BN * HDIM];
__device__ float g_hgraph[BN * HDIM];
__device__ float g_P[BN * HDIM];          // support @ Ws^T
__device__ float g_Q[BN * HDIM];          // support @ Wt^T
__device__ float g_s[BN * HDIM];
__device__ float g_t[BN * HDIM];
__device__ float g_hatt[BN * HDIM];
__device__ int   g_nbr[BN * MAXNB];
__device__ float g_nbrw[BN * MAXNB];
__device__ int   g_cnt[BN];
__device__ float g_sconst[HDIM];          // gc_b @ Ws^T + Ws_b
__device__ float g_tconst[HDIM];          // gc_b @ Wt^T + Wt_b
// transposed weights (coalesced GEMM access)
__device__ float g_Wih_t[IDIM * G4H];        // [64][512]
__device__ float g_Whh_t[HDIM * G4H];        // [128][512]
__device__ float g_Wst_t[HDIM * 2 * HDIM];   // [128][256]: col<128 Ws, col>=128 Wt
__device__ float g_comb_t[2 * HDIM * HDIM];  // [256][128]

__device__ __forceinline__ float sigm_fast(float x) {
    return __fdividef(1.0f, 1.0f + __expf(-x));
}
__device__ __forceinline__ float tanh_fast(float x) {
    float cx = fminf(fmaxf(x, -15.0f), 15.0f);
    float e = __expf(2.0f * cx);
    return __fdividef(e - 1.0f, e + 1.0f);
}

// ============================================================================
// K0: prep = weight transposes + adjacency scan + s/t bias-constants.
// ============================================================================
#define TW_TOTAL (IDIM*G4H + HDIM*G4H + HDIM*2*HDIM + 2*HDIM*HDIM)
#define NTB ((TW_TOTAL + 255) / 256)
#define SCANB ((BN + 7) / 8)
__global__ void __launch_bounds__(256)
prep_kernel(const float* __restrict__ W_ih, const float* __restrict__ W_hh,
            const float* __restrict__ Ws_w, const float* __restrict__ Wt_w,
            const float* __restrict__ comb_w, const float* __restrict__ adj,
            const float* __restrict__ gc_b, const float* __restrict__ Ws_b,
            const float* __restrict__ Wt_b)
{
    if (blockIdx.x < NTB) {
        int idx = blockIdx.x * 256 + threadIdx.x;
        if (idx < IDIM * G4H) {                       // Wih_t [64][512]
            int k = idx >> 9, g = idx & 511;
            g_Wih_t[idx] = __ldg(W_ih + g * IDIM + k);
            return;
        }
        idx -= IDIM * G4H;
        if (idx < HDIM * G4H) {                       // Whh_t [128][512]
            int k = idx >> 9, g = idx & 511;
            g_Whh_t[idx] = __ldg(W_hh + g * HDIM + k);
            return;
        }
        idx -= HDIM * G4H;
        if (idx < HDIM * 2 * HDIM) {                  // Wst_t [128][256]
            int k = idx >> 8, o = idx & 255;
            g_Wst_t[idx] = (o < HDIM) ? __ldg(Ws_w + o * HDIM + k)
                                      : __ldg(Wt_w + (o - HDIM) * HDIM + k);
            return;
        }
        idx -= HDIM * 2 * HDIM;
        if (idx < 2 * HDIM * HDIM) {                  // comb_t [256][128]
            int k = idx >> 7, o = idx & 127;
            g_comb_t[idx] = __ldg(comb_w + o * 2 * HDIM + k);
        }
        return;
    }

    if (blockIdx.x < NTB + SCANB) {
        // ---- adjacency scan: 8 warps, one row per warp, ballot compaction ----
        const int lane = threadIdx.x & 31;
        const int wrp  = threadIdx.x >> 5;
        const int row  = (blockIdx.x - NTB) * 8 + wrp;
        if (row >= BN) return;
        const int b = row / NNODES;
        const int i = row % NNODES;
        const float* arow = adj + (size_t)b * NNODES * NNODES + (size_t)i * NNODES;

        int cnt = 0;
        const unsigned lt = (1u << lane) - 1u;
        for (int j0 = 0; j0 < NNODES; j0 += 32) {
            int j = j0 + lane;
            float a = (j < NNODES) ? __ldg(arow + j) : 0.0f;
            unsigned m = __ballot_sync(0xffffffffu, a != 0.0f);
            int pos = cnt + __popc(m & lt);
            if (a != 0.0f && pos < MAXNB) {
                g_nbr[row * MAXNB + pos]  = j;
                g_nbrw[row * MAXNB + pos] = a;
            }
            cnt += __popc(m);
        }
        if (lane == 0) g_cnt[row] = min(cnt, MAXNB);
        return;
    }

    // ---- bias constants: sconst = gc_b @ Ws^T + Ws_b; tconst likewise ----
    __shared__ float gb[HDIM];
    int tid = threadIdx.x;
    if (tid < HDIM) gb[tid] = __ldg(gc_b + tid);
    __syncthreads();
    int o = tid & 127;
    const float* W = (tid < HDIM) ? (Ws_w + o * HDIM) : (Wt_w + o * HDIM);
    float acc = (tid < HDIM) ? __ldg(Ws_b + o) : __ldg(Wt_b + o);
#pragma unroll 8
    for (int k = 0; k < HDIM; k++)
        acc += gb[k] * __ldg(W + k);
    if (tid < HDIM) g_sconst[o] = acc;
    else            g_tconst[o] = acc;
}

// ============================================================================
// K1: LSTM gates GEMM.  Grid (325, 4), 128 thr, 4 nodes/block (m=4).
// ============================================================================
#define LM 4
__global__ void __launch_bounds__(128)
lstm_gemm_kernel(const float* __restrict__ x, const float* __restrict__ h,
                 const float* __restrict__ b_ih, const float* __restrict__ b_hh)
{
    __shared__ __align__(16) float sx[LM][IDIM];
    __shared__ __align__(16) float sh[LM][HDIM];

    const int node0 = blockIdx.x * LM;
    const int o = threadIdx.x;
    const int g = blockIdx.y * HDIM + o;

    for (int idx = o; idx < LM * IDIM; idx += 128) {
        int m = idx >> 6, k = idx & 63;
        sx[m][k] = x[(node0 + m) * IDIM + k];
    }
    for (int idx = o; idx < LM * HDIM; idx += 128) {
        int m = idx >> 7, k = idx & 127;
        sh[m][k] = h[(node0 + m) * HDIM + k];
    }
    __syncthreads();

    float acc[LM];
    const float bb = __ldg(b_ih + g) + __ldg(b_hh + g);
#pragma unroll
    for (int m = 0; m < LM; m++) acc[m] = bb;

#pragma unroll 4
    for (int k4 = 0; k4 < IDIM / 4; k4++) {
        int k = k4 * 4;
        float w0 = g_Wih_t[(k + 0) * G4H + g];
        float w1 = g_Wih_t[(k + 1) * G4H + g];
        float w2 = g_Wih_t[(k + 2) * G4H + g];
        float w3 = g_Wih_t[(k + 3) * G4H + g];
#pragma unroll
        for (int m = 0; m < LM; m++) {
            float4 a = *((const float4*)&sx[m][k]);
            acc[m] += a.x * w0 + a.y * w1 + a.z * w2 + a.w * w3;
        }
    }
#pragma unroll 4
    for (int k4 = 0; k4 < HDIM / 4; k4++) {
        int k = k4 * 4;
        float w0 = g_Whh_t[(k + 0) * G4H + g];
        float w1 = g_Whh_t[(k + 1) * G4H + g];
        float w2 = g_Whh_t[(k + 2) * G4H + g];
        float w3 = g_Whh_t[(k + 3) * G4H + g];
#pragma unroll
        for (int m = 0; m < LM; m++) {
            float4 a = *((const float4*)&sh[m][k]);
            acc[m] += a.x * w0 + a.y * w1 + a.z * w2 + a.w * w3;
        }
    }
#pragma unroll
    for (int m = 0; m < LM; m++)
        g_gates[(node0 + m) * G4H + g] = acc[m];
}

// ============================================================================
// K2: LSTM activations + support GEMM (m=2).  650 blocks, 128 threads.
// ============================================================================
__global__ void __launch_bounds__(128)
act_support_kernel(const float* __restrict__ c, const float* __restrict__ gc_w,
                   float* __restrict__ c_out)
{
    __shared__ float shh[2][HDIM];
    const int node0 = blockIdx.x * 2;
    const int u = threadIdx.x;

#pragma unroll
    for (int m = 0; m < 2; m++) {
        int node = node0 + m;
        const float* gb = g_gates + node * G4H;
        float ig = sigm_fast(gb[u]);
        float fg = sigm_fast(gb[HDIM + u]);
        float gg = tanh_fast(gb[2 * HDIM + u]);
        float og = sigm_fast(gb[3 * HDIM + u]);
        float cc = fg * c[node * HDIM + u] + ig * gg;
        float hh = og * tanh_fast(cc);
        c_out[node * HDIM + u] = cc;
        g_h_lstm[node * HDIM + u] = hh;
        shh[m][u] = hh;
    }
    __syncthreads();

    const int o = u;
    float a0 = 0.f, a1 = 0.f;
#pragma unroll 4
    for (int k = 0; k < HDIM; k++) {
        float w = __ldg(gc_w + k * HDIM + o);
        a0 += shh[0][k] * w;
        a1 += shh[1][k] * w;
    }
    g_support[node0 * HDIM + o] = a0;
    g_support[(node0 + 1) * HDIM + o] = a1;
}

// ============================================================================
// K3: P|Q GEMM, m=4.  Grid (325, 2): y=0 -> P (Ws cols), y=1 -> Q (Wt cols).
// ============================================================================
__global__ void __launch_bounds__(128)
pq_kernel()
{
    __shared__ __align__(16) float sA[LM][HDIM];
    const int node0 = blockIdx.x * LM;
    const int o = threadIdx.x;
    const int oc = blockIdx.y * HDIM + o;   // column in fused Wst [128][256]

    for (int idx = o; idx < LM * HDIM; idx += 128) {
        int m = idx >> 7, k = idx & 127;
        sA[m][k] = g_support[(node0 + m) * HDIM + k];
    }
    __syncthreads();

    float acc[LM] = {0.f, 0.f, 0.f, 0.f};
#pragma unroll 4
    for (int k4 = 0; k4 < HDIM / 4; k4++) {
        int k = k4 * 4;
        float w0 = g_Wst_t[(k + 0) * 2 * HDIM + oc];
        float w1 = g_Wst_t[(k + 1) * 2 * HDIM + oc];
        float w2 = g_Wst_t[(k + 2) * 2 * HDIM + oc];
        float w3 = g_Wst_t[(k + 3) * 2 * HDIM + oc];
#pragma unroll
        for (int m = 0; m < LM; m++) {
            float4 a = *((const float4*)&sA[m][k]);
            acc[m] += a.x * w0 + a.y * w1 + a.z * w2 + a.w * w3;
        }
    }
    float* C = blockIdx.y ? g_Q : g_P;
#pragma unroll
    for (int m = 0; m < LM; m++)
        C[(node0 + m) * HDIM + o] = acc[m];
}

// ============================================================================
// K4: triple sparse gather (no weight reads).  1300 blocks, 128 threads.
//   hgraph = adj-gather(support) + gc_b
//   s      = adj-gather(P) + sconst ;  t = adj-gather(Q) + tconst
// ============================================================================
__global__ void __launch_bounds__(128)
gather_kernel(const float* __restrict__ gc_b)
{
    const int row = blockIdx.x;
    const int b = row / NNODES;
    const int tid = threadIdx.x;

    __shared__ int   lst[MAXNB];
    __shared__ float wv[MAXNB];

    const int cn = g_cnt[row];
    for (int t = tid; t < cn; t += 128) {
        lst[t] = g_nbr[row * MAXNB + t];
        wv[t]  = g_nbrw[row * MAXNB + t];
    }
    __syncthreads();

    const int u = tid;
    float ah = __ldg(gc_b + u);
    float as = g_sconst[u];
    float at = g_tconst[u];
    const size_t base = (size_t)b * NNODES * HDIM + u;
    for (int t = 0; t < cn; t++) {
        size_t off = base + (size_t)lst[t] * HDIM;
        float w = wv[t];
        ah += w * g_support[off];
        as += w * g_P[off];
        at += w * g_Q[off];
    }
    g_hgraph[row * HDIM + u] = ah;
    g_s[row * HDIM + u] = as;
    g_t[row * HDIM + u] = at;
}

// ============================================================================
// K5: attention + softmax + context + LayerNorm.  1300 blocks, 128 threads.
// ============================================================================
__global__ void __launch_bounds__(128)
attn_kernel(const float* __restrict__ v, const float* __restrict__ ln_g,
            const float* __restrict__ ln_b)
{
    const int row = blockIdx.x;
    const int b = row / NNODES;
    const int tid = threadIdx.x;
    const int lane = tid & 31;
    const int wrp = tid >> 5;

    __shared__ float s_sh[HDIM];
    __shared__ float v_sh[HDIM];
    __shared__ float sc[MAXNB];
    __shared__ int   lst[MAXNB];
    __shared__ float red1[4], red2[4];

    s_sh[tid] = g_s[row * HDIM + tid];
    v_sh[tid] = __ldg(v + tid);
    const int cn = g_cnt[row];
    for (int t = tid; t < cn; t += 128) lst[t] = g_nbr[row * MAXNB + t];
    __syncthreads();

    // scores: 4 warps t-strided; lanes over features
    const float* tb = g_t + (size_t)b * NNODES * HDIM;
    for (int t = wrp; t < cn; t += 4) {
        const float* tj = tb + (size_t)lst[t] * HDIM;
        float p = 0.0f;
#pragma unroll
        for (int q = 0; q < 4; q++) {
            int u = lane + q * 32;
            p += tanh_fast(s_sh[u] + __ldg(tj + u)) * v_sh[u];
        }
#pragma unroll
        for (int off = 16; off > 0; off >>= 1)
            p += __shfl_xor_sync(0xffffffffu, p, off);
        if (lane == 0) sc[t] = p;
    }
    __syncthreads();

    // softmax (warp 0)
    if (wrp == 0) {
        float mx = -1e30f;
        for (int t = lane; t < cn; t += 32) mx = fmaxf(mx, sc[t]);
#pragma unroll
        for (int off = 16; off > 0; off >>= 1)
            mx = fmaxf(mx, __shfl_xor_sync(0xffffffffu, mx, off));
        float sm = 0.0f;
        for (int t = lane; t < cn; t += 32) {
            float e = __expf(sc[t] - mx);
            sc[t] = e;
            sm += e;
        }
#pragma unroll
        for (int off = 16; off > 0; off >>= 1)
            sm += __shfl_xor_sync(0xffffffffu, sm, off);
        float inv = __fdividef(1.0f, sm);
        for (int t = lane; t < cn; t += 32) sc[t] *= inv;
    }
    __syncthreads();

    // context
    const int u = tid;
    float acc = 0.0f;
    const float* hgb = g_hgraph + (size_t)b * NNODES * HDIM;
    for (int t = 0; t < cn; t++)
        acc += sc[t] * __ldg(hgb + (size_t)lst[t] * HDIM + u);

    // LayerNorm
    float s1 = acc, s2 = acc * acc;
#pragma unroll
    for (int off = 16; off > 0; off >>= 1) {
        s1 += __shfl_xor_sync(0xffffffffu, s1, off);
        s2 += __shfl_xor_sync(0xffffffffu, s2, off);
    }
    if (lane == 0) { red1[wrp] = s1; red2[wrp] = s2; }
    __syncthreads();
    float tot1 = red1[0] + red1[1] + red1[2] + red1[3];
    float tot2 = red2[0] + red2[1] + red2[2] + red2[3];
    float mu = tot1 * (1.0f / HDIM);
    float var = tot2 * (1.0f / HDIM) - mu * mu;
    g_hatt[row * HDIM + u] =
        __ldg(ln_g + u) * (acc - mu) * rsqrtf(var + LN_EPS) + __ldg(ln_b + u);
}

// ============================================================================
// K6: combine GEMM, m=2:  out = h_lstm @ W1^T + h_att @ W2^T + comb_b.
// 650 blocks, 128 threads, K=256.
// ============================================================================
__global__ void __launch_bounds__(128)
comb_kernel(const float* __restrict__ comb_b, float* __restrict__ out)
{
    __shared__ __align__(16) float shl[2][HDIM];
    __shared__ __align__(16) float sha[2][HDIM];
    const int node0 = blockIdx.x * 2;
    const int o = threadIdx.x;

    for (int idx = o; idx < 2 * HDIM; idx += 128) {
        int m = idx >> 7, k = idx & 127;
        shl[m][k] = g_h_lstm[(node0 + m) * HDIM + k];
        sha[m][k] = g_hatt[(node0 + m) * HDIM + k];
    }
    __syncthreads();

    const float cb = __ldg(comb_b + o);
    float a0 = cb, a1 = cb;
#pragma unroll 4
    for (int k4 = 0; k4 < HDIM / 4; k4++) {
        int k = k4 * 4;
        float w0 = g_comb_t[(k + 0) * HDIM + o];
        float w1 = g_comb_t[(k + 1) * HDIM + o];
        float w2 = g_comb_t[(k + 2) * HDIM + o];
        float w3 = g_comb_t[(k + 3) * HDIM + o];
        float4 p = *((const float4*)&shl[0][k]);
        float4 q = *((const float4*)&shl[1][k]);
        a0 += p.x * w0 + p.y * w1 + p.z * w2 + p.w * w3;
        a1 += q.x * w0 + q.y * w1 + q.z * w2 + q.w * w3;
    }
#pragma unroll 4
    for (int k4 = 0; k4 < HDIM / 4; k4++) {
        int k = k4 * 4;
        float w0 = g_comb_t[(HDIM + k + 0) * HDIM + o];
        float w1 = g_comb_t[(HDIM + k + 1) * HDIM + o];
        float w2 = g_comb_t[(HDIM + k + 2) * HDIM + o];
        float w3 = g_comb_t[(HDIM + k + 3) * HDIM + o];
        float4 p = *((const float4*)&sha[0][k]);
        float4 q = *((const float4*)&sha[1][k]);
        a0 += p.x * w0 + p.y * w1 + p.z * w2 + p.w * w3;
        a1 += q.x * w0 + q.y * w1 + q.z * w2 + q.w * w3;
    }
    out[node0 * HDIM + o] = a0;
    out[(node0 + 1) * HDIM + o] = a1;
}

// ============================================================================
extern "C" void kernel_launch(void* const* d_in, const int* in_sizes, int n_in,
                              void* d_out, int out_size)
{
    const float* x      = (const float*)d_in[0];
    const float* adj    = (const float*)d_in[1];
    const float* h      = (const float*)d_in[2];
    const float* c      = (const float*)d_in[3];
    const float* W_ih   = (const float*)d_in[4];
    const float* W_hh   = (const float*)d_in[5];
    const float* b_ih   = (const float*)d_in[6];
    const float* b_hh   = (const float*)d_in[7];
    const float* gc_w   = (const float*)d_in[8];
    const float* gc_b   = (const float*)d_in[9];
    const float* Ws_w   = (const float*)d_in[10];
    const float* Ws_b   = (const float*)d_in[11];
    const float* Wt_w   = (const float*)d_in[12];
    const float* Wt_b   = (const float*)d_in[13];
    const float* v      = (const float*)d_in[14];
    const float* ln_g   = (const float*)d_in[15];
    const float* ln_b   = (const float*)d_in[16];
    const float* comb_w = (const float*)d_in[17];
    const float* comb_b = (const float*)d_in[18];

    float* out = (float*)d_out;              // h_new, then c_lstm
    float* c_out = out + (size_t)BN * HDIM;

    prep_kernel<<<NTB + SCANB + 1, 256>>>(W_ih, W_hh, Ws_w, Wt_w, comb_w, adj,
                                          gc_b, Ws_b, Wt_b);
    dim3 lstm_grid(BN / LM, 4);                        // 325 x 4 = 1300
    lstm_gemm_kernel<<<lstm_grid, 128>>>(x, h, b_ih, b_hh);
    act_support_kernel<<<BN / 2, 128>>>(c, gc_w, c_out);          // 650
    dim3 pq_grid(BN / LM, 2);                          // 325 x 2 = 650
    pq_kernel<<<pq_grid, 128>>>();
    gather_kernel<<<BN, 128>>>(gc_b);                  // 1300
    attn_kernel<<<BN, 128>>>(v, ln_g, ln_b);           // 1300
    comb_kernel<<<BN / 2, 128>>>(comb_b, out);         // 650
}